// round 4
// baseline (speedup 1.0000x reference)
#include <cuda_runtime.h>
#include <cuda_bf16.h>

#define WIN 11
#define C1SSIM 1.0e-4f
#define C2SSIM 9.0e-4f

// scratch (allocation-free: __device__ globals)
__device__ float d_qn[15 * 64 * 441];   // normalized queries, [b][c][p]
__device__ float d_sn[25 * 64 * 441];   // normalized supports, [ns][c][p]
__device__ float d_mu[40 * 64 * 121];   // gaussian mean per image-channel (0..14 queries, 15..39 supports)
__device__ float d_sg[40 * 64 * 121];   // variance E[x^2]-mu^2
__device__ float d_part[15 * 5 * 64];   // per (b,n,c) ssim-sum over shots & pixels
__device__ int   d_count;               // block-completion counter for fused final reduce

__device__ __forceinline__ void gauss(float* g) {
    float s = 0.f;
#pragma unroll
    for (int i = 0; i < WIN; i++) {
        float d = (float)i - 5.0f;
        g[i] = expf(-d * d * (1.0f / 4.5f));  // 2*sigma^2 = 4.5
        s += g[i];
    }
    float inv = 1.0f / s;
#pragma unroll
    for (int i = 0; i < WIN; i++) g[i] *= inv;
}

// K1: per-position channel L2-normalize + transpose (p,c) -> (c,p)
__global__ void k_norm(const float* __restrict__ x1, const float* __restrict__ x2) {
    int img = blockIdx.x;            // 0..39
    int p0 = blockIdx.y * 32;        // position tile
    int np = min(32, 441 - p0);
    const float* src = (img < 15) ? (x1 + img * 441 * 64) : (x2 + (img - 15) * 441 * 64);
    float* dst = (img < 15) ? (d_qn + img * 64 * 441) : (d_sn + (img - 15) * 64 * 441);

    __shared__ float t[64][33];
    __shared__ float inv[32];

    for (int i = threadIdx.x; i < np * 64; i += 256) {
        int p = i >> 6, c = i & 63;
        t[c][p] = src[(p0 + p) * 64 + c];
    }
    __syncthreads();
    if (threadIdx.x < np) {
        int p = threadIdx.x;
        float s = 0.f;
#pragma unroll
        for (int c = 0; c < 64; c++) { float v = t[c][p]; s += v * v; }
        inv[p] = rsqrtf(s);
    }
    __syncthreads();
    for (int i = threadIdx.x; i < 64 * np; i += 256) {
        int c = i / np, p = i - c * np;
        dst[c * 441 + p0 + p] = t[c][p] * inv[p];
    }
}

// K2: warp-per-channel stats: separable gaussian of x and x^2 -> mu, sigma^2. No block barriers.
__global__ void k_stats2() {
    __shared__ float x[4][448];
    __shared__ float h1[4][232];
    __shared__ float h2[4][232];
    float g[WIN];
    gauss(g);
    int tid = threadIdx.x, w = tid >> 5, lane = tid & 31;
    int id = blockIdx.x * 4 + w;     // 0..2559 == img*64 + c
    int img = id >> 6, c = id & 63;
    const float* row = (img < 15) ? (d_qn + (img * 64 + c) * 441)
                                  : (d_sn + ((img - 15) * 64 + c) * 441);
    float* xw = x[w]; float* h1w = h1[w]; float* h2w = h2[w];

    for (int i = lane; i < 441; i += 32) xw[i] = row[i];
    __syncwarp();
    for (int o = lane; o < 231; o += 32) {   // 21 rows x 11 cols
        int r = o / 11, j = o - 11 * r;
        const float* xr = xw + r * 21 + j;
        float s1 = 0.f, s2 = 0.f;
#pragma unroll
        for (int k = 0; k < WIN; k++) { float v = xr[k]; s1 = fmaf(g[k], v, s1); s2 = fmaf(g[k] * v, v, s2); }
        h1w[o] = s1; h2w[o] = s2;
    }
    __syncwarp();
    for (int o = lane; o < 121; o += 32) {   // 11 x 11
        int i = o / 11, j = o - 11 * i;
        float m = 0.f, m2 = 0.f;
#pragma unroll
        for (int k = 0; k < WIN; k++) {
            m  = fmaf(g[k], h1w[(i + k) * 11 + j], m);
            m2 = fmaf(g[k], h2w[(i + k) * 11 + j], m2);
        }
        d_mu[id * 121 + o] = m;
        d_sg[id * 121 + o] = m2 - m * m;
    }
}

// K3: per (b,n,c) block, WARP-PER-SHOT (5 warps), + fused final reduce in last block
__global__ void k_cross2(float* __restrict__ out) {
    int c = blockIdx.x, n = blockIdx.y, b = blockIdx.z;
    __shared__ float q[441];
    __shared__ float z[5][448];
    __shared__ float h[5][232];
    __shared__ float red[5];
    __shared__ int is_last;
    float g[WIN];
    gauss(g);
    int tid = threadIdx.x, w = tid >> 5, lane = tid & 31;

    const float* qrow = d_qn + (b * 64 + c) * 441;
    for (int i = tid; i < 441; i += 160) q[i] = qrow[i];
    __syncthreads();

    // warp w handles shot s = w
    int ns = n * 5 + w;
    const float* srow = d_sn + (ns * 64 + c) * 441;
    float* zw = z[w]; float* hw = h[w];

    for (int i = lane; i < 441; i += 32) zw[i] = q[i] * srow[i];
    __syncwarp();
    for (int o = lane; o < 231; o += 32) {
        int r = o / 11, j = o - 11 * r;
        const float* zr = zw + r * 21 + j;
        float sv = 0.f;
#pragma unroll
        for (int k = 0; k < WIN; k++) sv = fmaf(g[k], zr[k], sv);
        hw[o] = sv;
    }
    __syncwarp();

    const float* mu1p = d_mu + (b * 64 + c) * 121;
    const float* sg1p = d_sg + (b * 64 + c) * 121;
    const float* mu2p = d_mu + ((15 + ns) * 64 + c) * 121;
    const float* sg2p = d_sg + ((15 + ns) * 64 + c) * 121;

    float ws = 0.f;
    for (int o = lane; o < 121; o += 32) {
        int i = o / 11, j = o - 11 * i;
        float t12 = 0.f;
#pragma unroll
        for (int k = 0; k < WIN; k++) t12 = fmaf(g[k], hw[(i + k) * 11 + j], t12);
        float mu1 = mu1p[o], mu2 = mu2p[o];
        float sg1 = sg1p[o], sg2 = sg2p[o];
        float m12 = mu1 * mu2;
        float num = (2.f * m12 + C1SSIM) * (2.f * (t12 - m12) + C2SSIM);
        float den = (mu1 * mu1 + mu2 * mu2 + C1SSIM) * (sg1 + sg2 + C2SSIM);
        ws += num / den;
    }
#pragma unroll
    for (int off = 16; off > 0; off >>= 1) ws += __shfl_down_sync(0xffffffffu, ws, off);
    if (lane == 0) red[w] = ws;
    __syncthreads();

    if (tid == 0) {
        d_part[(b * 5 + n) * 64 + c] = red[0] + red[1] + red[2] + red[3] + red[4];
        __threadfence();
        int old = atomicAdd(&d_count, 1);
        is_last = (old == 64 * 5 * 15 - 1) ? 1 : 0;
    }
    __syncthreads();

    if (is_last) {
        __threadfence();  // acquire: make all blocks' d_part writes visible
        if (tid < 75) {
            const float* p = d_part + tid * 64;
            float s = 0.f;
#pragma unroll
            for (int k = 0; k < 64; k++) s += p[k];
            out[tid] = s * (1.0f / (64.0f * 121.0f));
        }
        if (tid == 0) d_count = 0;  // self-reset for next graph replay
    }
}

extern "C" void kernel_launch(void* const* d_in, const int* in_sizes, int n_in,
                              void* d_out, int out_size) {
    const float* x1 = (const float*)d_in[0];   // (15, 441, 64)
    const float* x2 = (const float*)d_in[1];   // (5, 5, 441, 64)
    float* out = (float*)d_out;                // (15, 5)

    dim3 g1(40, 14);
    k_norm<<<g1, 256>>>(x1, x2);
    k_stats2<<<640, 128>>>();
    dim3 g3(64, 5, 15);
    k_cross2<<<g3, 160>>>(out);
}